// round 1
// baseline (speedup 1.0000x reference)
#include <cuda_runtime.h>

#define ROWS  32768
#define BATCH 8
#define SDIM  4096
#define ADIM  48
#define GF    256
#define PDIM  32
#define EDIM  5
#define NBINS 65536
#define TM    32
#define STR   (TM + 2)

// ---------------- scratch (static device globals; no allocation) -------------
__device__ float g_X0[ROWS * 256];
__device__ float g_X1[ROWS * 256];
__device__ float g_X2[ROWS * 256];
__device__ int   g_cnt[ROWS * EDIM];
__device__ float g_scores[ROWS];
__device__ float g_PW[EDIM * 21 * 256];   // prefix sums of thermometer weight rows

// ---------------- prefix-sum of the one-hot block of combine_W ---------------
__global__ void init_pw_kernel(const float* __restrict__ cW) {
    int e = blockIdx.x, j = threadIdx.x;
    float run = 0.f;
    g_PW[(e * 21 + 0) * 256 + j] = 0.f;
    for (int l = 0; l < 20; l++) {
        run += cW[(e * 20 + l) * 256 + j];
        g_PW[(e * 21 + l + 1) * 256 + j] = run;
    }
}

// ---------------- prep: subset-weighted feature mean + inorm + counts --------
__global__ __launch_bounds__(256) void prep_kernel(
    const float* __restrict__ feat, const float* __restrict__ mask,
    const float* __restrict__ ohmat, const int* __restrict__ subs)
{
    __shared__ float ys[TM * 256];
    __shared__ float subm[TM * ADIM];
    __shared__ float sraw[TM * ADIM];
    __shared__ float smask[ADIM];
    __shared__ float sohs[ADIM * EDIM];
    __shared__ float sinv[TM];
    __shared__ float rowm[TM], rowr[TM];

    int tid  = threadIdx.x;
    int row0 = blockIdx.x * TM;          // 4096 % 32 == 0 -> block never crosses batch
    int b    = row0 >> 12;

    if (tid < ADIM) smask[tid] = mask[b * ADIM + tid];
    for (int idx = tid; idx < ADIM * EDIM; idx += 256)
        sohs[idx] = ohmat[b * ADIM * EDIM + idx];
    __syncthreads();

    for (int idx = tid; idx < TM * ADIM; idx += 256) {
        int r = idx / ADIM, a = idx - r * ADIM;
        float v = (float)subs[(row0 + r) * ADIM + a];
        sraw[idx] = v;
        subm[idx] = v * smask[a];
    }
    __syncthreads();

    if (tid < TM * EDIM) {               // per-subset element counts (exact ints)
        int r = tid / EDIM, e = tid - r * EDIM;
        float c = 0.f;
        for (int a = 0; a < ADIM; a++) c += sohs[a * EDIM + e] * sraw[r * ADIM + a];
        g_cnt[(row0 + r) * EDIM + e] = (int)(c + 0.5f);
    }
    if (tid < TM) {
        float sz = 0.f;
        for (int a = 0; a < ADIM; a++) sz += subm[tid * ADIM + a];
        sinv[tid] = 1.f / (sz + 1e-4f);
    }
    __syncthreads();

    float acc[TM];
    #pragma unroll
    for (int r = 0; r < TM; r++) acc[r] = 0.f;
    const float* fb = feat + b * ADIM * GF + tid;
    for (int a = 0; a < ADIM; a++) {
        float f = fb[a * GF] * smask[a];     // masked vertex feature (col = tid)
        #pragma unroll
        for (int r = 0; r < TM; r++) acc[r] += f * subm[r * ADIM + a];
    }
    #pragma unroll
    for (int r = 0; r < TM; r++) { acc[r] *= sinv[r]; ys[r * 256 + tid] = acc[r]; }
    __syncthreads();

    int wid = tid >> 5, lane = tid & 31;
    for (int i = 0; i < 4; i++) {            // batched instance-norm stats
        int r = wid * 4 + i;
        float s1 = 0.f, s2 = 0.f;
        #pragma unroll
        for (int q = 0; q < 8; q++) { float x = ys[r * 256 + lane + q * 32]; s1 += x; s2 += x * x; }
        #pragma unroll
        for (int o = 16; o; o >>= 1) {
            s1 += __shfl_xor_sync(0xffffffffu, s1, o);
            s2 += __shfl_xor_sync(0xffffffffu, s2, o);
        }
        if (!lane) {
            float m = s1 * (1.f / 256.f);
            rowm[r] = m;
            rowr[r] = rsqrtf(s2 * (1.f / 256.f) - m * m + 1e-5f);
        }
    }
    __syncthreads();
    #pragma unroll
    for (int r = 0; r < TM; r++)
        g_X0[(row0 + r) * 256 + tid] = (acc[r] - rowm[r]) * rowr[r];
}

// ---------------- fused dense layer: K=256 GEMM (f32x2) + epilogue ----------
// ACT: 0 = relu, 1 = leaky(0.01). PW: add thermometer prefix rows.
// INORM: instance-norm over the 256 outputs. SCORE: emit score instead of Y.
template <int ACT, bool PW, bool INORM, bool SCORE>
__global__ __launch_bounds__(256) void mlp_kernel(
    const float* __restrict__ X, const float* __restrict__ W,
    const float* __restrict__ bias, float* __restrict__ Y,
    const float* __restrict__ scoreW, const float* __restrict__ scoreB)
{
    __shared__ float sbuf[256 * STR];        // x^T tile, later reused for reductions
    __shared__ float rowm[TM], rowr[TM];
    __shared__ int   scnt[TM * EDIM];

    int tid  = threadIdx.x;
    int row0 = blockIdx.x * TM;

    for (int idx = tid; idx < TM * 256; idx += 256) {    // transposed, coalesced GMEM
        int r = idx >> 8, k = idx & 255;
        sbuf[k * STR + r] = X[((row0 + r) << 8) + k];
    }
    if (PW) {
        if (tid < TM * EDIM) {
            int c = g_cnt[row0 * EDIM + tid];
            scnt[tid] = c > 20 ? 20 : c;
        }
    }
    __syncthreads();

    int j = tid;                              // output column
    unsigned long long acc[16];
    #pragma unroll
    for (int r = 0; r < 16; r++) acc[r] = 0ull;

    const float* Wc = W + j;
    #pragma unroll 4
    for (int k = 0; k < 256; k++) {
        float w = Wc[k << 8];
        unsigned long long w2;
        asm("mov.b64 %0, {%1, %1};" : "=l"(w2) : "r"(__float_as_uint(w)));
        const unsigned long long* xp = (const unsigned long long*)(sbuf + k * STR);
        #pragma unroll
        for (int r = 0; r < 16; r++) {       // row pairs, packed fp32x2 FMA
            unsigned long long x2 = xp[r];
            asm("fma.rn.f32x2 %0, %1, %2, %0;" : "+l"(acc[r]) : "l"(x2), "l"(w2));
        }
    }

    float bj = bias[j];
    float val[TM];
    #pragma unroll
    for (int r = 0; r < 16; r++) {
        float2 v = *(float2*)(&acc[r]);
        val[2 * r]     = v.x + bj;
        val[2 * r + 1] = v.y + bj;
    }
    if (PW) {
        #pragma unroll 4
        for (int r = 0; r < TM; r++) {
            float s = 0.f;
            #pragma unroll
            for (int e = 0; e < EDIM; e++)
                s += g_PW[(e * 21 + scnt[r * EDIM + e]) * 256 + j];
            val[r] += s;
        }
    }
    #pragma unroll
    for (int r = 0; r < TM; r++) {
        if (ACT == 0) val[r] = fmaxf(val[r], 0.f);
        else          val[r] = val[r] > 0.f ? val[r] : 0.01f * val[r];
    }

    int wid = tid >> 5, lane = tid & 31;
    if (INORM) {
        __syncthreads();                      // everyone done reading x tile
        #pragma unroll
        for (int r = 0; r < TM; r++) sbuf[r * 256 + tid] = val[r];
        __syncthreads();
        for (int i = 0; i < 4; i++) {
            int r = wid * 4 + i;
            float s1 = 0.f, s2 = 0.f;
            #pragma unroll
            for (int q = 0; q < 8; q++) { float x = sbuf[r * 256 + lane + q * 32]; s1 += x; s2 += x * x; }
            #pragma unroll
            for (int o = 16; o; o >>= 1) {
                s1 += __shfl_xor_sync(0xffffffffu, s1, o);
                s2 += __shfl_xor_sync(0xffffffffu, s2, o);
            }
            if (!lane) {
                float m = s1 * (1.f / 256.f);
                rowm[r] = m;
                rowr[r] = rsqrtf(s2 * (1.f / 256.f) - m * m + 1e-5f);
            }
        }
        __syncthreads();
        #pragma unroll
        for (int r = 0; r < TM; r++) val[r] = (val[r] - rowm[r]) * rowr[r];
    }

    if (SCORE) {
        float ws = scoreW[j];
        __syncthreads();
        #pragma unroll
        for (int r = 0; r < TM; r++) sbuf[r * 256 + tid] = val[r] * ws;
        __syncthreads();
        for (int i = 0; i < 4; i++) {
            int r = wid * 4 + i;
            float s1 = 0.f;
            #pragma unroll
            for (int q = 0; q < 8; q++) s1 += sbuf[r * 256 + lane + q * 32];
            #pragma unroll
            for (int o = 16; o; o >>= 1) s1 += __shfl_xor_sync(0xffffffffu, s1, o);
            if (!lane) g_scores[row0 + r] = s1 + scoreB[0];
        }
    } else {
        #pragma unroll
        for (int r = 0; r < TM; r++) Y[((row0 + r) << 8) + j] = val[r];
    }
}

// ---------------- per-batch softmax over 4096 scores ------------------------
__global__ void softmax_kernel(float* __restrict__ probs) {
    __shared__ float sm[8];
    int b = blockIdx.x, tid = threadIdx.x;
    int wid = tid >> 5, lane = tid & 31;
    float v[16];
    float mx = -1e30f;
    #pragma unroll
    for (int i = 0; i < 16; i++) { v[i] = g_scores[b * SDIM + i * 256 + tid]; mx = fmaxf(mx, v[i]); }
    #pragma unroll
    for (int o = 16; o; o >>= 1) mx = fmaxf(mx, __shfl_xor_sync(0xffffffffu, mx, o));
    if (!lane) sm[wid] = mx;
    __syncthreads();
    mx = sm[0];
    #pragma unroll
    for (int q = 1; q < 8; q++) mx = fmaxf(mx, sm[q]);
    float s = 0.f;
    #pragma unroll
    for (int i = 0; i < 16; i++) { v[i] = expf(v[i] - mx); s += v[i]; }
    #pragma unroll
    for (int o = 16; o; o >>= 1) s += __shfl_xor_sync(0xffffffffu, s, o);
    __syncthreads();
    if (!lane) sm[wid] = s;
    __syncthreads();
    s = 0.f;
    #pragma unroll
    for (int q = 0; q < 8; q++) s += sm[q];
    float inv = 1.f / s;
    #pragma unroll
    for (int i = 0; i < 16; i++) probs[b * SDIM + i * 256 + tid] = v[i] * inv;
}

// ---------------- scatter-add weighted intensities into spectral bins --------
__global__ void scatter_kernel(const int* __restrict__ mass, const float* __restrict__ inten,
                               const float* __restrict__ probs, float* __restrict__ spect) {
    int i  = blockIdx.x * 256 + threadIdx.x;      // < B*S*P = 1048576
    int bs = i >> 5;                              // b*S + s
    int b  = i >> 17;
    float w = inten[i] * probs[bs];
    atomicAdd(spect + (b << 16) + mass[i], w);
}

// ---------------- launch sequence -------------------------------------------
extern "C" void kernel_launch(void* const* d_in, const int* in_sizes, int n_in,
                              void* d_out, int out_size)
{
    const float* feat  = (const float*)d_in[0];
    const float* mask  = (const float*)d_in[1];
    const float* ohm   = (const float*)d_in[2];
    // d_in[3] = adj_oh (unused), d_in[5] = atom_subsets_peaks (unused)
    const int*   subs  = (const int*)d_in[4];
    const int*   mass  = (const int*)d_in[6];
    const float* inten = (const float*)d_in[7];
    const float* cW  = (const float*)d_in[8];
    const float* cb  = (const float*)d_in[9];
    const float* w1  = (const float*)d_in[10];
    const float* b1  = (const float*)d_in[11];
    const float* w2a = (const float*)d_in[12];
    const float* b2a = (const float*)d_in[13];
    const float* w2b = (const float*)d_in[14];
    const float* b2b = (const float*)d_in[15];
    const float* sW  = (const float*)d_in[16];
    const float* sB  = (const float*)d_in[17];

    float* out   = (float*)d_out;
    float* spect = out;                     // (B, NBINS)
    float* probs = out + BATCH * NBINS;     // (B, S)

    float *x0, *x1, *x2;
    cudaGetSymbolAddress((void**)&x0, g_X0);
    cudaGetSymbolAddress((void**)&x1, g_X1);
    cudaGetSymbolAddress((void**)&x2, g_X2);

    init_pw_kernel<<<EDIM, 256>>>(cW);
    prep_kernel<<<ROWS / TM, 256>>>(feat, mask, ohm, subs);

    // combine (feature half of W + prefix-summed OH rows), relu, inorm
    mlp_kernel<0, true,  true,  false><<<ROWS / TM, 256>>>(x0, cW + 100 * 256, cb, x1, nullptr, nullptr);
    // l1: relu
    mlp_kernel<0, false, false, false><<<ROWS / TM, 256>>>(x1, w1,  b1,  x2, nullptr, nullptr);
    // l2a: leaky
    mlp_kernel<1, false, false, false><<<ROWS / TM, 256>>>(x2, w2a, b2a, x1, nullptr, nullptr);
    // l2b: relu(leaky(y)) == relu(y), inorm, then fused score head
    mlp_kernel<0, false, true,  true ><<<ROWS / TM, 256>>>(x1, w2b, b2b, nullptr, sW, sB);

    softmax_kernel<<<BATCH, 256>>>(probs);
    cudaMemsetAsync(spect, 0, (size_t)BATCH * NBINS * sizeof(float), 0);
    scatter_kernel<<<BATCH * SDIM * PDIM / 256, 256>>>(mass, inten, probs, spect);
}

// round 2
// speedup vs baseline: 1.0529x; 1.0529x over previous
#include <cuda_runtime.h>

#define ROWS  32768
#define BATCH 8
#define SDIM  4096
#define ADIM  48
#define GF    256
#define PDIM  32
#define EDIM  5
#define NBINS 65536
#define TM    32
#define BM    64          // rows per mlp block
#define XSTR  66          // padded word stride of x^T tile (264B, 8B-aligned)

typedef unsigned long long ull;

// ---------------- scratch (static device globals; no allocation) -------------
__device__ float g_X0[ROWS * 256];
__device__ float g_X1[ROWS * 256];
__device__ float g_X2[ROWS * 256];
__device__ int   g_cnt[ROWS * EDIM];
__device__ float g_scores[ROWS];
__device__ float g_PW[EDIM * 21 * 256];   // prefix sums of thermometer weight rows

// ---------------- prefix-sum of the one-hot block of combine_W ---------------
__global__ void init_pw_kernel(const float* __restrict__ cW) {
    int e = blockIdx.x, j = threadIdx.x;
    float run = 0.f;
    g_PW[(e * 21 + 0) * 256 + j] = 0.f;
    for (int l = 0; l < 20; l++) {
        run += cW[(e * 20 + l) * 256 + j];
        g_PW[(e * 21 + l + 1) * 256 + j] = run;
    }
}

// ---------------- prep: subset-weighted feature mean + inorm + counts --------
__global__ __launch_bounds__(256) void prep_kernel(
    const float* __restrict__ feat, const float* __restrict__ mask,
    const float* __restrict__ ohmat, const int* __restrict__ subs)
{
    __shared__ float ys[TM * 256];
    __shared__ float subm[TM * ADIM];
    __shared__ float sraw[TM * ADIM];
    __shared__ float smask[ADIM];
    __shared__ float sohs[ADIM * EDIM];
    __shared__ float sinv[TM];
    __shared__ float rowm[TM], rowr[TM];

    int tid  = threadIdx.x;
    int row0 = blockIdx.x * TM;
    int b    = row0 >> 12;

    if (tid < ADIM) smask[tid] = mask[b * ADIM + tid];
    for (int idx = tid; idx < ADIM * EDIM; idx += 256)
        sohs[idx] = ohmat[b * ADIM * EDIM + idx];
    __syncthreads();

    for (int idx = tid; idx < TM * ADIM; idx += 256) {
        int r = idx / ADIM, a = idx - r * ADIM;
        float v = (float)subs[(row0 + r) * ADIM + a];
        sraw[idx] = v;
        subm[idx] = v * smask[a];
    }
    __syncthreads();

    if (tid < TM * EDIM) {
        int r = tid / EDIM, e = tid - r * EDIM;
        float c = 0.f;
        for (int a = 0; a < ADIM; a++) c += sohs[a * EDIM + e] * sraw[r * ADIM + a];
        g_cnt[(row0 + r) * EDIM + e] = (int)(c + 0.5f);
    }
    if (tid < TM) {
        float sz = 0.f;
        for (int a = 0; a < ADIM; a++) sz += subm[tid * ADIM + a];
        sinv[tid] = 1.f / (sz + 1e-4f);
    }
    __syncthreads();

    float acc[TM];
    #pragma unroll
    for (int r = 0; r < TM; r++) acc[r] = 0.f;
    const float* fb = feat + b * ADIM * GF + tid;
    for (int a = 0; a < ADIM; a++) {
        float f = fb[a * GF] * smask[a];
        #pragma unroll
        for (int r = 0; r < TM; r++) acc[r] += f * subm[r * ADIM + a];
    }
    #pragma unroll
    for (int r = 0; r < TM; r++) { acc[r] *= sinv[r]; ys[r * 256 + tid] = acc[r]; }
    __syncthreads();

    int wid = tid >> 5, lane = tid & 31;
    for (int i = 0; i < 4; i++) {
        int r = wid * 4 + i;
        float s1 = 0.f, s2 = 0.f;
        #pragma unroll
        for (int q = 0; q < 8; q++) { float x = ys[r * 256 + lane + q * 32]; s1 += x; s2 += x * x; }
        #pragma unroll
        for (int o = 16; o; o >>= 1) {
            s1 += __shfl_xor_sync(0xffffffffu, s1, o);
            s2 += __shfl_xor_sync(0xffffffffu, s2, o);
        }
        if (!lane) {
            float m = s1 * (1.f / 256.f);
            rowm[r] = m;
            rowr[r] = rsqrtf(s2 * (1.f / 256.f) - m * m + 1e-5f);
        }
    }
    __syncthreads();
    #pragma unroll
    for (int r = 0; r < TM; r++)
        g_X0[(row0 + r) * 256 + tid] = (acc[r] - rowm[r]) * rowr[r];
}

// ---------------- fused dense layer: 64x256 block, 8x8 register tile ---------
// ACT: 0 = relu, 1 = leaky(0.01). PW: add thermometer prefix rows.
// INORM: instance-norm over the 256 outputs. SCORE: emit score instead of Y.
template <int ACT, bool PW, bool INORM, bool SCORE>
__global__ __launch_bounds__(256) void mlp_kernel(
    const float* __restrict__ X, const float* __restrict__ W,
    const float* __restrict__ bias, float* __restrict__ Y,
    const float* __restrict__ scoreW, const float* __restrict__ scoreB)
{
    __shared__ float xs[256 * XSTR];          // x^T: xs[k*XSTR + r] = X[row0+r][k]
    __shared__ int   scnt[BM * EDIM];

    int tid = threadIdx.x;
    int tx  = tid & 31;                        // col group: cols tx*8 .. tx*8+7
    int ty  = tid >> 5;                        // row group: rows ty*8 .. ty*8+7
    int row0 = blockIdx.x * BM;

    // load x^T tile (coalesced LDG, 2-way-conflict STS)
    for (int idx = tid; idx < BM * 256; idx += 256) {
        int k = idx & 255, r = idx >> 8;
        xs[k * XSTR + r] = X[((row0 + r) << 8) + k];
    }
    if (PW) {
        for (int idx = tid; idx < BM * EDIM; idx += 256) {
            int c = g_cnt[row0 * EDIM + idx];
            scnt[idx] = c > 20 ? 20 : c;
        }
    }
    __syncthreads();

    ull acc[32];
    #pragma unroll
    for (int i = 0; i < 32; i++) acc[i] = 0ull;

    const float4* Wp = (const float4*)W + tx * 2;   // per k: + k*64
    #pragma unroll 2
    for (int k = 0; k < 256; k++) {
        float4 wa = Wp[k * 64];
        float4 wb = Wp[k * 64 + 1];
        ull w2[8];
        asm("mov.b64 %0,{%1,%1};" : "=l"(w2[0]) : "r"(__float_as_uint(wa.x)));
        asm("mov.b64 %0,{%1,%1};" : "=l"(w2[1]) : "r"(__float_as_uint(wa.y)));
        asm("mov.b64 %0,{%1,%1};" : "=l"(w2[2]) : "r"(__float_as_uint(wa.z)));
        asm("mov.b64 %0,{%1,%1};" : "=l"(w2[3]) : "r"(__float_as_uint(wa.w)));
        asm("mov.b64 %0,{%1,%1};" : "=l"(w2[4]) : "r"(__float_as_uint(wb.x)));
        asm("mov.b64 %0,{%1,%1};" : "=l"(w2[5]) : "r"(__float_as_uint(wb.y)));
        asm("mov.b64 %0,{%1,%1};" : "=l"(w2[6]) : "r"(__float_as_uint(wb.z)));
        asm("mov.b64 %0,{%1,%1};" : "=l"(w2[7]) : "r"(__float_as_uint(wb.w)));
        const ull* xp = (const ull*)(xs + k * XSTR) + ty * 4;   // row pairs ty*8..
        ull x0 = xp[0], x1 = xp[1], x2 = xp[2], x3 = xp[3];
        #pragma unroll
        for (int c = 0; c < 8; c++) {
            asm("fma.rn.f32x2 %0, %1, %2, %0;" : "+l"(acc[c])      : "l"(x0), "l"(w2[c]));
            asm("fma.rn.f32x2 %0, %1, %2, %0;" : "+l"(acc[8 + c])  : "l"(x1), "l"(w2[c]));
            asm("fma.rn.f32x2 %0, %1, %2, %0;" : "+l"(acc[16 + c]) : "l"(x2), "l"(w2[c]));
            asm("fma.rn.f32x2 %0, %1, %2, %0;" : "+l"(acc[24 + c]) : "l"(x3), "l"(w2[c]));
        }
    }

    // unpack + bias
    float4 ba = *((const float4*)bias + tx * 2);
    float4 bb = *((const float4*)bias + tx * 2 + 1);
    float bj[8] = {ba.x, ba.y, ba.z, ba.w, bb.x, bb.y, bb.z, bb.w};
    float val[8][8];
    #pragma unroll
    for (int rp = 0; rp < 4; rp++)
        #pragma unroll
        for (int c = 0; c < 8; c++) {
            float2 v = *(float2*)&acc[rp * 8 + c];
            val[2 * rp][c]     = v.x + bj[c];
            val[2 * rp + 1][c] = v.y + bj[c];
        }

    if (PW) {
        #pragma unroll
        for (int r = 0; r < 8; r++) {
            int rr = ty * 8 + r;
            float s[8] = {0.f, 0.f, 0.f, 0.f, 0.f, 0.f, 0.f, 0.f};
            #pragma unroll
            for (int e = 0; e < EDIM; e++) {
                const float* p = g_PW + (e * 21 + scnt[rr * EDIM + e]) * 256 + tx * 8;
                float4 pa = *(const float4*)p;
                float4 pb = *(const float4*)(p + 4);
                s[0] += pa.x; s[1] += pa.y; s[2] += pa.z; s[3] += pa.w;
                s[4] += pb.x; s[5] += pb.y; s[6] += pb.z; s[7] += pb.w;
            }
            #pragma unroll
            for (int c = 0; c < 8; c++) val[r][c] += s[c];
        }
    }

    #pragma unroll
    for (int r = 0; r < 8; r++)
        #pragma unroll
        for (int c = 0; c < 8; c++) {
            float v = val[r][c];
            val[r][c] = (ACT == 0) ? fmaxf(v, 0.f) : (v > 0.f ? v : 0.01f * v);
        }

    if (INORM) {
        #pragma unroll
        for (int r = 0; r < 8; r++) {
            float s1 = 0.f, s2 = 0.f;
            #pragma unroll
            for (int c = 0; c < 8; c++) { float x = val[r][c]; s1 += x; s2 += x * x; }
            #pragma unroll
            for (int o = 16; o; o >>= 1) {
                s1 += __shfl_xor_sync(0xffffffffu, s1, o);
                s2 += __shfl_xor_sync(0xffffffffu, s2, o);
            }
            float m  = s1 * (1.f / 256.f);
            float rs = rsqrtf(s2 * (1.f / 256.f) - m * m + 1e-5f);
            #pragma unroll
            for (int c = 0; c < 8; c++) val[r][c] = (val[r][c] - m) * rs;
        }
    }

    if (SCORE) {
        float4 sa = *((const float4*)scoreW + tx * 2);
        float4 sb = *((const float4*)scoreW + tx * 2 + 1);
        float sw[8] = {sa.x, sa.y, sa.z, sa.w, sb.x, sb.y, sb.z, sb.w};
        float sbv = scoreB[0];
        #pragma unroll
        for (int r = 0; r < 8; r++) {
            float s = 0.f;
            #pragma unroll
            for (int c = 0; c < 8; c++) s += val[r][c] * sw[c];
            #pragma unroll
            for (int o = 16; o; o >>= 1) s += __shfl_xor_sync(0xffffffffu, s, o);
            if (!tx) g_scores[row0 + ty * 8 + r] = s + sbv;
        }
    } else {
        #pragma unroll
        for (int r = 0; r < 8; r++) {
            float4* yp = (float4*)(Y + ((row0 + ty * 8 + r) << 8)) + tx * 2;
            yp[0] = make_float4(val[r][0], val[r][1], val[r][2], val[r][3]);
            yp[1] = make_float4(val[r][4], val[r][5], val[r][6], val[r][7]);
        }
    }
}

// ---------------- per-batch softmax over 4096 scores ------------------------
__global__ void softmax_kernel(float* __restrict__ probs) {
    __shared__ float sm[8];
    int b = blockIdx.x, tid = threadIdx.x;
    int wid = tid >> 5, lane = tid & 31;
    float v[16];
    float mx = -1e30f;
    #pragma unroll
    for (int i = 0; i < 16; i++) { v[i] = g_scores[b * SDIM + i * 256 + tid]; mx = fmaxf(mx, v[i]); }
    #pragma unroll
    for (int o = 16; o; o >>= 1) mx = fmaxf(mx, __shfl_xor_sync(0xffffffffu, mx, o));
    if (!lane) sm[wid] = mx;
    __syncthreads();
    mx = sm[0];
    #pragma unroll
    for (int q = 1; q < 8; q++) mx = fmaxf(mx, sm[q]);
    float s = 0.f;
    #pragma unroll
    for (int i = 0; i < 16; i++) { v[i] = expf(v[i] - mx); s += v[i]; }
    #pragma unroll
    for (int o = 16; o; o >>= 1) s += __shfl_xor_sync(0xffffffffu, s, o);
    __syncthreads();
    if (!lane) sm[wid] = s;
    __syncthreads();
    s = 0.f;
    #pragma unroll
    for (int q = 0; q < 8; q++) s += sm[q];
    float inv = 1.f / s;
    #pragma unroll
    for (int i = 0; i < 16; i++) probs[b * SDIM + i * 256 + tid] = v[i] * inv;
}

// ---------------- scatter-add weighted intensities into spectral bins --------
__global__ void scatter_kernel(const int* __restrict__ mass, const float* __restrict__ inten,
                               const float* __restrict__ probs, float* __restrict__ spect) {
    int i  = blockIdx.x * 256 + threadIdx.x;
    int bs = i >> 5;
    int b  = i >> 17;
    float w = inten[i] * probs[bs];
    atomicAdd(spect + (b << 16) + mass[i], w);
}

// ---------------- launch sequence -------------------------------------------
extern "C" void kernel_launch(void* const* d_in, const int* in_sizes, int n_in,
                              void* d_out, int out_size)
{
    const float* feat  = (const float*)d_in[0];
    const float* mask  = (const float*)d_in[1];
    const float* ohm   = (const float*)d_in[2];
    const int*   subs  = (const int*)d_in[4];
    const int*   mass  = (const int*)d_in[6];
    const float* inten = (const float*)d_in[7];
    const float* cW  = (const float*)d_in[8];
    const float* cb  = (const float*)d_in[9];
    const float* w1  = (const float*)d_in[10];
    const float* b1  = (const float*)d_in[11];
    const float* w2a = (const float*)d_in[12];
    const float* b2a = (const float*)d_in[13];
    const float* w2b = (const float*)d_in[14];
    const float* b2b = (const float*)d_in[15];
    const float* sW  = (const float*)d_in[16];
    const float* sB  = (const float*)d_in[17];

    float* out   = (float*)d_out;
    float* spect = out;                     // (B, NBINS)
    float* probs = out + BATCH * NBINS;     // (B, S)

    float *x0, *x1, *x2;
    cudaGetSymbolAddress((void**)&x0, g_X0);
    cudaGetSymbolAddress((void**)&x1, g_X1);
    cudaGetSymbolAddress((void**)&x2, g_X2);

    init_pw_kernel<<<EDIM, 256>>>(cW);
    prep_kernel<<<ROWS / TM, 256>>>(feat, mask, ohm, subs);

    mlp_kernel<0, true,  true,  false><<<ROWS / BM, 256>>>(x0, cW + 100 * 256, cb, x1, nullptr, nullptr);
    mlp_kernel<0, false, false, false><<<ROWS / BM, 256>>>(x1, w1,  b1,  x2, nullptr, nullptr);
    mlp_kernel<1, false, false, false><<<ROWS / BM, 256>>>(x2, w2a, b2a, x1, nullptr, nullptr);
    mlp_kernel<0, false, true,  true ><<<ROWS / BM, 256>>>(x1, w2b, b2b, nullptr, sW, sB);

    softmax_kernel<<<BATCH, 256>>>(probs);
    cudaMemsetAsync(spect, 0, (size_t)BATCH * NBINS * sizeof(float), 0);
    scatter_kernel<<<BATCH * SDIM * PDIM / 256, 256>>>(mass, inten, probs, spect);
}

// round 3
// speedup vs baseline: 1.3391x; 1.2717x over previous
#include <cuda_runtime.h>

#define ROWS  32768
#define BATCH 8
#define SDIM  4096
#define ADIM  48
#define GF    256
#define PDIM  32
#define EDIM  5
#define NBINS 65536
#define TM    32
#define BM    64          // rows per mlp block
#define XSTR  72          // padded word stride of x^T tile (8B-aligned, 8-way STS)
#define KC    16          // k-chunk staged per cp.async group
#define NCHUNK (256 / KC)

typedef unsigned long long ull;

// ---------------- scratch (static device globals; no allocation) -------------
__device__ float g_X0[ROWS * 256];
__device__ float g_X1[ROWS * 256];
__device__ float g_X2[ROWS * 256];
__device__ int   g_cnt[ROWS * EDIM];
__device__ float g_scores[ROWS];
__device__ float g_PW[EDIM * 21 * 256];   // prefix sums of thermometer weight rows

__device__ __forceinline__ unsigned smem_u32(const void* p) {
    unsigned a;
    asm("{ .reg .u64 t; cvta.to.shared.u64 t, %1; cvt.u32.u64 %0, t; }" : "=r"(a) : "l"(p));
    return a;
}

// ---------------- prefix-sum of the one-hot block of combine_W ---------------
__global__ void init_pw_kernel(const float* __restrict__ cW) {
    int e = blockIdx.x, j = threadIdx.x;
    float run = 0.f;
    g_PW[(e * 21 + 0) * 256 + j] = 0.f;
    for (int l = 0; l < 20; l++) {
        run += cW[(e * 20 + l) * 256 + j];
        g_PW[(e * 21 + l + 1) * 256 + j] = run;
    }
}

// ---------------- prep: subset-weighted feature mean + inorm + counts --------
__global__ __launch_bounds__(256) void prep_kernel(
    const float* __restrict__ feat, const float* __restrict__ mask,
    const float* __restrict__ ohmat, const int* __restrict__ subs)
{
    __shared__ float ys[TM * 256];
    __shared__ float subm[TM * ADIM];
    __shared__ float sraw[TM * ADIM];
    __shared__ float smask[ADIM];
    __shared__ float sohs[ADIM * EDIM];
    __shared__ float sinv[TM];
    __shared__ float rowm[TM], rowr[TM];

    int tid  = threadIdx.x;
    int row0 = blockIdx.x * TM;
    int b    = row0 >> 12;

    if (tid < ADIM) smask[tid] = mask[b * ADIM + tid];
    for (int idx = tid; idx < ADIM * EDIM; idx += 256)
        sohs[idx] = ohmat[b * ADIM * EDIM + idx];
    __syncthreads();

    for (int idx = tid; idx < TM * ADIM; idx += 256) {
        int r = idx / ADIM, a = idx - r * ADIM;
        float v = (float)subs[(row0 + r) * ADIM + a];
        sraw[idx] = v;
        subm[idx] = v * smask[a];
    }
    __syncthreads();

    if (tid < TM * EDIM) {
        int r = tid / EDIM, e = tid - r * EDIM;
        float c = 0.f;
        for (int a = 0; a < ADIM; a++) c += sohs[a * EDIM + e] * sraw[r * ADIM + a];
        g_cnt[(row0 + r) * EDIM + e] = (int)(c + 0.5f);
    }
    if (tid < TM) {
        float sz = 0.f;
        for (int a = 0; a < ADIM; a++) sz += subm[tid * ADIM + a];
        sinv[tid] = 1.f / (sz + 1e-4f);
    }
    __syncthreads();

    float acc[TM];
    #pragma unroll
    for (int r = 0; r < TM; r++) acc[r] = 0.f;
    const float* fb = feat + b * ADIM * GF + tid;
    for (int a = 0; a < ADIM; a++) {
        float f = fb[a * GF] * smask[a];
        #pragma unroll
        for (int r = 0; r < TM; r++) acc[r] += f * subm[r * ADIM + a];
    }
    #pragma unroll
    for (int r = 0; r < TM; r++) { acc[r] *= sinv[r]; ys[r * 256 + tid] = acc[r]; }
    __syncthreads();

    int wid = tid >> 5, lane = tid & 31;
    for (int i = 0; i < 4; i++) {
        int r = wid * 4 + i;
        float s1 = 0.f, s2 = 0.f;
        #pragma unroll
        for (int q = 0; q < 8; q++) { float x = ys[r * 256 + lane + q * 32]; s1 += x; s2 += x * x; }
        #pragma unroll
        for (int o = 16; o; o >>= 1) {
            s1 += __shfl_xor_sync(0xffffffffu, s1, o);
            s2 += __shfl_xor_sync(0xffffffffu, s2, o);
        }
        if (!lane) {
            float m = s1 * (1.f / 256.f);
            rowm[r] = m;
            rowr[r] = rsqrtf(s2 * (1.f / 256.f) - m * m + 1e-5f);
        }
    }
    __syncthreads();
    #pragma unroll
    for (int r = 0; r < TM; r++)
        g_X0[(row0 + r) * 256 + tid] = (acc[r] - rowm[r]) * rowr[r];
}

// ---------------- fused dense layer: cp.async W pipeline, 8x8 reg tile -------
// Thread (tx,ty): rows ty*8..+7, cols {tx*4..+3} U {128+tx*4..+3}
template <int ACT, bool PW, bool INORM, bool SCORE>
__global__ __launch_bounds__(256, 2) void mlp_kernel(
    const float* __restrict__ X, const float* __restrict__ W,
    const float* __restrict__ bias, float* __restrict__ Y,
    const float* __restrict__ scoreW, const float* __restrict__ scoreB)
{
    extern __shared__ float smem[];
    float* xs = smem;                         // 256 * XSTR
    float* ws = smem + 256 * XSTR;            // 2 * KC * 256
    __shared__ int scnt[BM * EDIM];

    int tid = threadIdx.x;
    int tx  = tid & 31;
    int ty  = tid >> 5;
    int row0 = blockIdx.x * BM;

    unsigned wsAddr = smem_u32(ws);

    // kick off chunk 0 of W while we transpose X
    {
        const float4* src = (const float4*)W + tid;
        unsigned dst = wsAddr + tid * 16;
        #pragma unroll
        for (int i = 0; i < 4; i++)
            asm volatile("cp.async.ca.shared.global [%0], [%1], 16;"
                         :: "r"(dst + i * 256 * 16), "l"(src + i * 256));
        asm volatile("cp.async.commit_group;");
    }

    // x^T tile: coalesced LDG, 8-way-conflict STS (startup only)
    for (int idx = tid; idx < BM * 256; idx += 256) {
        int k = idx & 255, r = idx >> 8;
        xs[k * XSTR + r] = X[((row0 + r) << 8) + k];
    }
    if (PW) {
        for (int idx = tid; idx < BM * EDIM; idx += 256) {
            int c = g_cnt[row0 * EDIM + idx];
            scnt[idx] = c > 20 ? 20 : c;
        }
    }

    ull acc[32];
    #pragma unroll
    for (int i = 0; i < 32; i++) acc[i] = 0ull;

    for (int c = 0; c < NCHUNK; c++) {
        int buf = c & 1;
        if (c + 1 < NCHUNK) {                 // prefetch next chunk
            const float4* src = (const float4*)(W + (c + 1) * KC * 256) + tid;
            unsigned dst = wsAddr + (buf ^ 1) * (KC * 256 * 4) + tid * 16;
            #pragma unroll
            for (int i = 0; i < 4; i++)
                asm volatile("cp.async.ca.shared.global [%0], [%1], 16;"
                             :: "r"(dst + i * 256 * 16), "l"(src + i * 256));
            asm volatile("cp.async.commit_group;");
            asm volatile("cp.async.wait_group 1;");
        } else {
            asm volatile("cp.async.wait_group 0;");
        }
        __syncthreads();

        const float* wb_base = ws + buf * (KC * 256) + tx * 4;
        const float* xb_base = xs + c * KC * XSTR + ty * 8;
        #pragma unroll 4
        for (int kk = 0; kk < KC; kk++) {
            float4 wa = *(const float4*)(wb_base + kk * 256);
            float4 wb = *(const float4*)(wb_base + kk * 256 + 128);
            ull w2[8];
            asm("mov.b64 %0,{%1,%1};" : "=l"(w2[0]) : "r"(__float_as_uint(wa.x)));
            asm("mov.b64 %0,{%1,%1};" : "=l"(w2[1]) : "r"(__float_as_uint(wa.y)));
            asm("mov.b64 %0,{%1,%1};" : "=l"(w2[2]) : "r"(__float_as_uint(wa.z)));
            asm("mov.b64 %0,{%1,%1};" : "=l"(w2[3]) : "r"(__float_as_uint(wa.w)));
            asm("mov.b64 %0,{%1,%1};" : "=l"(w2[4]) : "r"(__float_as_uint(wb.x)));
            asm("mov.b64 %0,{%1,%1};" : "=l"(w2[5]) : "r"(__float_as_uint(wb.y)));
            asm("mov.b64 %0,{%1,%1};" : "=l"(w2[6]) : "r"(__float_as_uint(wb.z)));
            asm("mov.b64 %0,{%1,%1};" : "=l"(w2[7]) : "r"(__float_as_uint(wb.w)));
            const ull* xp = (const ull*)(xb_base + kk * XSTR);
            ull x0 = xp[0], x1 = xp[1], x2 = xp[2], x3 = xp[3];
            #pragma unroll
            for (int q = 0; q < 8; q++) {
                asm("fma.rn.f32x2 %0, %1, %2, %0;" : "+l"(acc[q])      : "l"(x0), "l"(w2[q]));
                asm("fma.rn.f32x2 %0, %1, %2, %0;" : "+l"(acc[8 + q])  : "l"(x1), "l"(w2[q]));
                asm("fma.rn.f32x2 %0, %1, %2, %0;" : "+l"(acc[16 + q]) : "l"(x2), "l"(w2[q]));
                asm("fma.rn.f32x2 %0, %1, %2, %0;" : "+l"(acc[24 + q]) : "l"(x3), "l"(w2[q]));
            }
        }
        __syncthreads();
    }

    // unpack + bias (cols tx*4..+3 and 128+tx*4..+3)
    float4 ba = *(const float4*)(bias + tx * 4);
    float4 bb = *(const float4*)(bias + 128 + tx * 4);
    float bj[8] = {ba.x, ba.y, ba.z, ba.w, bb.x, bb.y, bb.z, bb.w};
    float val[8][8];
    #pragma unroll
    for (int rp = 0; rp < 4; rp++)
        #pragma unroll
        for (int q = 0; q < 8; q++) {
            float2 v = *(float2*)&acc[rp * 8 + q];
            val[2 * rp][q]     = v.x + bj[q];
            val[2 * rp + 1][q] = v.y + bj[q];
        }

    if (PW) {
        #pragma unroll
        for (int r = 0; r < 8; r++) {
            int rr = ty * 8 + r;
            float s[8] = {0.f, 0.f, 0.f, 0.f, 0.f, 0.f, 0.f, 0.f};
            #pragma unroll
            for (int e = 0; e < EDIM; e++) {
                const float* p = g_PW + (e * 21 + scnt[rr * EDIM + e]) * 256;
                float4 pa = *(const float4*)(p + tx * 4);
                float4 pb = *(const float4*)(p + 128 + tx * 4);
                s[0] += pa.x; s[1] += pa.y; s[2] += pa.z; s[3] += pa.w;
                s[4] += pb.x; s[5] += pb.y; s[6] += pb.z; s[7] += pb.w;
            }
            #pragma unroll
            for (int q = 0; q < 8; q++) val[r][q] += s[q];
        }
    }

    #pragma unroll
    for (int r = 0; r < 8; r++)
        #pragma unroll
        for (int q = 0; q < 8; q++) {
            float v = val[r][q];
            val[r][q] = (ACT == 0) ? fmaxf(v, 0.f) : (v > 0.f ? v : 0.01f * v);
        }

    if (INORM) {
        #pragma unroll
        for (int r = 0; r < 8; r++) {
            float s1 = 0.f, s2 = 0.f;
            #pragma unroll
            for (int q = 0; q < 8; q++) { float x = val[r][q]; s1 += x; s2 += x * x; }
            #pragma unroll
            for (int o = 16; o; o >>= 1) {
                s1 += __shfl_xor_sync(0xffffffffu, s1, o);
                s2 += __shfl_xor_sync(0xffffffffu, s2, o);
            }
            float m  = s1 * (1.f / 256.f);
            float rs = rsqrtf(s2 * (1.f / 256.f) - m * m + 1e-5f);
            #pragma unroll
            for (int q = 0; q < 8; q++) val[r][q] = (val[r][q] - m) * rs;
        }
    }

    if (SCORE) {
        float4 sa = *(const float4*)(scoreW + tx * 4);
        float4 sb = *(const float4*)(scoreW + 128 + tx * 4);
        float sw[8] = {sa.x, sa.y, sa.z, sa.w, sb.x, sb.y, sb.z, sb.w};
        float sbv = scoreB[0];
        #pragma unroll
        for (int r = 0; r < 8; r++) {
            float s = 0.f;
            #pragma unroll
            for (int q = 0; q < 8; q++) s += val[r][q] * sw[q];
            #pragma unroll
            for (int o = 16; o; o >>= 1) s += __shfl_xor_sync(0xffffffffu, s, o);
            if (!tx) g_scores[row0 + ty * 8 + r] = s + sbv;
        }
    } else {
        #pragma unroll
        for (int r = 0; r < 8; r++) {
            float* yp = Y + ((row0 + ty * 8 + r) << 8);
            *(float4*)(yp + tx * 4)       = make_float4(val[r][0], val[r][1], val[r][2], val[r][3]);
            *(float4*)(yp + 128 + tx * 4) = make_float4(val[r][4], val[r][5], val[r][6], val[r][7]);
        }
    }
}

// ---------------- per-batch softmax over 4096 scores ------------------------
__global__ void softmax_kernel(float* __restrict__ probs) {
    __shared__ float sm[8];
    int b = blockIdx.x, tid = threadIdx.x;
    int wid = tid >> 5, lane = tid & 31;
    float v[16];
    float mx = -1e30f;
    #pragma unroll
    for (int i = 0; i < 16; i++) { v[i] = g_scores[b * SDIM + i * 256 + tid]; mx = fmaxf(mx, v[i]); }
    #pragma unroll
    for (int o = 16; o; o >>= 1) mx = fmaxf(mx, __shfl_xor_sync(0xffffffffu, mx, o));
    if (!lane) sm[wid] = mx;
    __syncthreads();
    mx = sm[0];
    #pragma unroll
    for (int q = 1; q < 8; q++) mx = fmaxf(mx, sm[q]);
    float s = 0.f;
    #pragma unroll
    for (int i = 0; i < 16; i++) { v[i] = expf(v[i] - mx); s += v[i]; }
    #pragma unroll
    for (int o = 16; o; o >>= 1) s += __shfl_xor_sync(0xffffffffu, s, o);
    __syncthreads();
    if (!lane) sm[wid] = s;
    __syncthreads();
    s = 0.f;
    #pragma unroll
    for (int q = 0; q < 8; q++) s += sm[q];
    float inv = 1.f / s;
    #pragma unroll
    for (int i = 0; i < 16; i++) probs[b * SDIM + i * 256 + tid] = v[i] * inv;
}

// ---------------- scatter-add weighted intensities into spectral bins --------
__global__ void scatter_kernel(const int* __restrict__ mass, const float* __restrict__ inten,
                               const float* __restrict__ probs, float* __restrict__ spect) {
    int i  = blockIdx.x * 256 + threadIdx.x;
    int bs = i >> 5;
    int b  = i >> 17;
    float w = inten[i] * probs[bs];
    atomicAdd(spect + (b << 16) + mass[i], w);
}

// ---------------- launch sequence -------------------------------------------
#define MLP_SMEM ((256 * XSTR + 2 * KC * 256) * (int)sizeof(float))

extern "C" void kernel_launch(void* const* d_in, const int* in_sizes, int n_in,
                              void* d_out, int out_size)
{
    const float* feat  = (const float*)d_in[0];
    const float* mask  = (const float*)d_in[1];
    const float* ohm   = (const float*)d_in[2];
    const int*   subs  = (const int*)d_in[4];
    const int*   mass  = (const int*)d_in[6];
    const float* inten = (const float*)d_in[7];
    const float* cW  = (const float*)d_in[8];
    const float* cb  = (const float*)d_in[9];
    const float* w1  = (const float*)d_in[10];
    const float* b1  = (const float*)d_in[11];
    const float* w2a = (const float*)d_in[12];
    const float* b2a = (const float*)d_in[13];
    const float* w2b = (const float*)d_in[14];
    const float* b2b = (const float*)d_in[15];
    const float* sW  = (const float*)d_in[16];
    const float* sB  = (const float*)d_in[17];

    float* out   = (float*)d_out;
    float* spect = out;                     // (B, NBINS)
    float* probs = out + BATCH * NBINS;     // (B, S)

    float *x0, *x1, *x2;
    cudaGetSymbolAddress((void**)&x0, g_X0);
    cudaGetSymbolAddress((void**)&x1, g_X1);
    cudaGetSymbolAddress((void**)&x2, g_X2);

    static int smem_set = 0;
    if (!smem_set) {
        cudaFuncSetAttribute(mlp_kernel<0, true,  true,  false>, cudaFuncAttributeMaxDynamicSharedMemorySize, MLP_SMEM);
        cudaFuncSetAttribute(mlp_kernel<0, false, false, false>, cudaFuncAttributeMaxDynamicSharedMemorySize, MLP_SMEM);
        cudaFuncSetAttribute(mlp_kernel<1, false, false, false>, cudaFuncAttributeMaxDynamicSharedMemorySize, MLP_SMEM);
        cudaFuncSetAttribute(mlp_kernel<0, false, true,  true >, cudaFuncAttributeMaxDynamicSharedMemorySize, MLP_SMEM);
        smem_set = 1;
    }

    init_pw_kernel<<<EDIM, 256>>>(cW);
    prep_kernel<<<ROWS / TM, 256>>>(feat, mask, ohm, subs);

    mlp_kernel<0, true,  true,  false><<<ROWS / BM, 256, MLP_SMEM>>>(x0, cW + 100 * 256, cb, x1, nullptr, nullptr);
    mlp_kernel<0, false, false, false><<<ROWS / BM, 256, MLP_SMEM>>>(x1, w1,  b1,  x2, nullptr, nullptr);
    mlp_kernel<1, false, false, false><<<ROWS / BM, 256, MLP_SMEM>>>(x2, w2a, b2a, x1, nullptr, nullptr);
    mlp_kernel<0, false, true,  true ><<<ROWS / BM, 256, MLP_SMEM>>>(x1, w2b, b2b, nullptr, sW, sB);

    softmax_kernel<<<BATCH, 256>>>(probs);
    cudaMemsetAsync(spect, 0, (size_t)BATCH * NBINS * sizeof(float), 0);
    scatter_kernel<<<BATCH * SDIM * PDIM / 256, 256>>>(mass, inten, probs, spect);
}

// round 7
// speedup vs baseline: 1.4958x; 1.1170x over previous
#include <cuda_runtime.h>
#include <cuda_bf16.h>
#include <cstdint>

#define ROWS  32768
#define BATCH 8
#define SDIM  4096
#define ADIM  48
#define GF    256
#define EDIM  5
#define NBINS 65536
#define TM    32

// gemm tiling
#define BMR    64                    // CTA rows
#define XSTRB  528                   // X smem row stride bytes (264 bf16)
#define WSTRB  80                    // W smem row stride bytes (40 bf16)
#define XH_OFF 0
#define XL_OFF 33792                 // 64*528
#define WS_OFF 67584                 // X total
#define WBUF   40960                 // per double-buffer slot (hi+lo)
#define WLO    20480                 // lo offset inside slot
#define GEMM_DYN (WS_OFF + 2 * WBUF) // 149504

typedef unsigned long long ull;

// ---------------- scratch (static device globals; no allocation) -------------
__device__ __nv_bfloat16 g_Ah0[ROWS * 256], g_Al0[ROWS * 256];
__device__ __nv_bfloat16 g_Ah1[ROWS * 256], g_Al1[ROWS * 256];
__device__ __nv_bfloat16 g_Ah2[ROWS * 256], g_Al2[ROWS * 256];
__device__ __nv_bfloat16 g_WTh[4][256 * 256], g_WTl[4][256 * 256];
__device__ float g_PWadd[ROWS * 256];
__device__ int   g_cnt[ROWS * EDIM];
__device__ float g_scores[ROWS];
__device__ float g_PW[EDIM * 21 * 256];

// ---------------- helpers ----------------------------------------------------
__device__ __forceinline__ uint32_t smem_u32(const void* p) {
    uint32_t a;
    asm("{ .reg .u64 t; cvta.to.shared.u64 t, %1; cvt.u32.u64 %0, t; }" : "=r"(a) : "l"(p));
    return a;
}
__device__ __forceinline__ void ldsm4(uint32_t* r, uint32_t a) {
    asm volatile("ldmatrix.sync.aligned.m8n8.x4.shared.b16 {%0,%1,%2,%3}, [%4];"
                 : "=r"(r[0]), "=r"(r[1]), "=r"(r[2]), "=r"(r[3]) : "r"(a));
}
__device__ __forceinline__ void mma16816(float* d, const uint32_t* a, const uint32_t* b) {
    asm volatile("mma.sync.aligned.m16n8k16.row.col.f32.bf16.bf16.f32 "
                 "{%0,%1,%2,%3}, {%4,%5,%6,%7}, {%8,%9}, {%0,%1,%2,%3};"
                 : "+f"(d[0]), "+f"(d[1]), "+f"(d[2]), "+f"(d[3])
                 : "r"(a[0]), "r"(a[1]), "r"(a[2]), "r"(a[3]), "r"(b[0]), "r"(b[1]));
}
#define CPA16(dst, src) \
    asm volatile("cp.async.ca.shared.global [%0], [%1], 16;" :: "r"(dst), "l"(src))

// ---------------- prefix-sum of the one-hot block of combine_W ---------------
__global__ void init_pw_kernel(const float* __restrict__ cW) {
    int e = blockIdx.x, j = threadIdx.x;
    float run = 0.f;
    g_PW[(e * 21 + 0) * 256 + j] = 0.f;
    for (int l = 0; l < 20; l++) {
        run += cW[(e * 20 + l) * 256 + j];
        g_PW[(e * 21 + l + 1) * 256 + j] = run;
    }
}

// ---------------- W^T + bf16 hi/lo split ------------------------------------
__global__ void wt_kernel(const float* __restrict__ W, int layer) {
    int n = blockIdx.x, k = threadIdx.x;
    float w = W[k * 256 + n];
    __nv_bfloat16 h = __float2bfloat16(w);
    g_WTh[layer][n * 256 + k] = h;
    g_WTl[layer][n * 256 + k] = __float2bfloat16(w - __bfloat162float(h));
}

// ---------------- thermometer additive term per (row, col) -------------------
__global__ __launch_bounds__(256) void pwadd_kernel() {
    extern __shared__ float spw[];                 // 105*256 floats
    int tid = threadIdx.x;
    for (int i = tid; i < 105 * 256; i += 256) spw[i] = g_PW[i];
    __syncthreads();
    int row0 = blockIdx.x * 512;
    for (int rr = 0; rr < 512; rr++) {
        int row = row0 + rr;
        float s = 0.f;
        #pragma unroll
        for (int e = 0; e < EDIM; e++) {
            int c = g_cnt[row * EDIM + e];
            c = c > 20 ? 20 : c;
            s += spw[(e * 21 + c) * 256 + tid];
        }
        g_PWadd[row * 256 + tid] = s;
    }
}

// ---------------- prep: subset-weighted feature mean + inorm + counts --------
__global__ __launch_bounds__(256) void prep_kernel(
    const float* __restrict__ feat, const float* __restrict__ mask,
    const float* __restrict__ ohmat, const int* __restrict__ subs)
{
    __shared__ float ys[TM * 256];
    __shared__ float subm[TM * ADIM];
    __shared__ float sraw[TM * ADIM];
    __shared__ float smask[ADIM];
    __shared__ float sohs[ADIM * EDIM];
    __shared__ float sinv[TM];
    __shared__ float rowm[TM], rowr[TM];

    int tid  = threadIdx.x;
    int row0 = blockIdx.x * TM;
    int b    = row0 >> 12;

    if (tid < ADIM) smask[tid] = mask[b * ADIM + tid];
    for (int idx = tid; idx < ADIM * EDIM; idx += 256)
        sohs[idx] = ohmat[b * ADIM * EDIM + idx];
    __syncthreads();

    for (int idx = tid; idx < TM * ADIM; idx += 256) {
        int r = idx / ADIM, a = idx - r * ADIM;
        float v = (float)subs[(row0 + r) * ADIM + a];
        sraw[idx] = v;
        subm[idx] = v * smask[a];
    }
    __syncthreads();

    if (tid < TM * EDIM) {
        int r = tid / EDIM, e = tid - r * EDIM;
        float c = 0.f;
        for (int a = 0; a < ADIM; a++) c += sohs[a * EDIM + e] * sraw[r * ADIM + a];
        g_cnt[(row0 + r) * EDIM + e] = (int)(c + 0.5f);
    }
    if (tid < TM) {
        float sz = 0.f;
        for (int a = 0; a < ADIM; a++) sz += subm[tid * ADIM + a];
        sinv[tid] = 1.f / (sz + 1e-4f);
    }
    __syncthreads();

    float acc[TM];
    #pragma unroll
    for (int r = 0; r < TM; r++) acc[r] = 0.f;
    const float* fb = feat + b * ADIM * GF + tid;
    for (int a = 0; a < ADIM; a++) {
        float f = fb[a * GF] * smask[a];
        #pragma unroll
        for (int r = 0; r < TM; r++) acc[r] += f * subm[r * ADIM + a];
    }
    #pragma unroll
    for (int r = 0; r < TM; r++) { acc[r] *= sinv[r]; ys[r * 256 + tid] = acc[r]; }
    __syncthreads();

    int wid = tid >> 5, lane = tid & 31;
    for (int i = 0; i < 4; i++) {
        int r = wid * 4 + i;
        float s1 = 0.f, s2 = 0.f;
        #pragma unroll
        for (int q = 0; q < 8; q++) { float x = ys[r * 256 + lane + q * 32]; s1 += x; s2 += x * x; }
        #pragma unroll
        for (int o = 16; o; o >>= 1) {
            s1 += __shfl_xor_sync(0xffffffffu, s1, o);
            s2 += __shfl_xor_sync(0xffffffffu, s2, o);
        }
        if (!lane) {
            float m = s1 * (1.f / 256.f);
            rowm[r] = m;
            rowr[r] = rsqrtf(s2 * (1.f / 256.f) - m * m + 1e-5f);
        }
    }
    __syncthreads();
    #pragma unroll
    for (int r = 0; r < TM; r++) {
        float xv = (acc[r] - rowm[r]) * rowr[r];
        __nv_bfloat16 h = __float2bfloat16(xv);
        int o = (row0 + r) * 256 + tid;
        g_Ah0[o] = h;
        g_Al0[o] = __float2bfloat16(xv - __bfloat162float(h));
    }
}

// ---------------- HMMA bf16x3 GEMM: 64x256 tile, cp.async W pipeline ---------
template <int ACT, bool PWADD, bool INORM, bool SCORE>
__global__ __launch_bounds__(256) void gemm_kernel(
    const __nv_bfloat16* __restrict__ Ah, const __nv_bfloat16* __restrict__ Al,
    const __nv_bfloat16* __restrict__ Bh, const __nv_bfloat16* __restrict__ Bl,
    const float* __restrict__ bias,
    __nv_bfloat16* __restrict__ Yh, __nv_bfloat16* __restrict__ Yl,
    const float* __restrict__ scoreW, const float* __restrict__ scoreB)
{
    extern __shared__ unsigned char dsm[];
    __shared__ float sbias[256];
    __shared__ float sscw[256];
    __shared__ float ssum[256], ssq[256];
    __shared__ float rowm[BMR], rowr[BMR];

    int tid  = threadIdx.x;
    int wid  = tid >> 5, lane = tid & 31;
    int wm   = wid & 1;                 // 2 row-groups of 32
    int wn   = wid >> 1;                // 4 col-groups of 64
    int row0 = blockIdx.x * BMR;
    uint32_t sbase = smem_u32(dsm);

    sbias[tid] = bias[tid];
    if (SCORE) sscw[tid] = scoreW[tid];

    // ---- stage X tile (hi+lo) + W chunks 0,1 via cp.async ----
    #pragma unroll
    for (int t = 0; t < 8; t++) {
        int idx = tid + t * 256;                  // 0..2047
        int r = idx >> 5, seg = idx & 31;
        uint32_t d = sbase + r * XSTRB + seg * 16;
        CPA16(d,           Ah + ((row0 + r) << 8) + seg * 8);
        CPA16(d + XL_OFF,  Al + ((row0 + r) << 8) + seg * 8);
    }
    {   // chunk 0
        #pragma unroll
        for (int t = 0; t < 4; t++) {
            int idx = tid + t * 256;              // 0..1023
            int n = idx >> 2, seg = idx & 3;
            uint32_t d = sbase + WS_OFF + n * WSTRB + seg * 16;
            CPA16(d,       Bh + (n << 8) + seg * 8);
            CPA16(d + WLO, Bl + (n << 8) + seg * 8);
        }
        asm volatile("cp.async.commit_group;");
        #pragma unroll
        for (int t = 0; t < 4; t++) {             // chunk 1
            int idx = tid + t * 256;
            int n = idx >> 2, seg = idx & 3;
            uint32_t d = sbase + WS_OFF + WBUF + n * WSTRB + seg * 16;
            CPA16(d,       Bh + (n << 8) + 32 + seg * 8);
            CPA16(d + WLO, Bl + (n << 8) + 32 + seg * 8);
        }
        asm volatile("cp.async.commit_group;");
    }

    // lane-level ldmatrix base addresses
    uint32_t xaH = sbase + (wm * 32 + (lane & 15)) * XSTRB + (lane >> 4) * 16;
    uint32_t xaL = xaH + XL_OFF;
    uint32_t wa0 = sbase + WS_OFF +
                   (wn * 64 + (lane & 7) + ((lane >> 4) & 1) * 8) * WSTRB +
                   ((lane >> 3) & 1) * 16;

    float acc[2][8][4];
    #pragma unroll
    for (int mt = 0; mt < 2; mt++)
        #pragma unroll
        for (int nf = 0; nf < 8; nf++)
            #pragma unroll
            for (int q = 0; q < 4; q++) acc[mt][nf][q] = 0.f;

    for (int c = 0; c < 8; c++) {
        if (c < 7) asm volatile("cp.async.wait_group 1;" ::: "memory");
        else       asm volatile("cp.async.wait_group 0;" ::: "memory");
        __syncthreads();
        uint32_t wb = wa0 + (c & 1) * WBUF;

        #pragma unroll
        for (int half = 0; half < 2; half++) {
            int k16 = c * 2 + half;
            uint32_t Ahf[2][4], Alf[2][4];
            ldsm4(Ahf[0], xaH + k16 * 32);
            ldsm4(Ahf[1], xaH + 16 * XSTRB + k16 * 32);
            ldsm4(Alf[0], xaL + k16 * 32);
            ldsm4(Alf[1], xaL + 16 * XSTRB + k16 * 32);
            #pragma unroll
            for (int ng = 0; ng < 4; ng++) {
                uint32_t Bh4[4], Bl4[4];
                ldsm4(Bh4, wb + ng * 16 * WSTRB + half * 32);
                ldsm4(Bl4, wb + WLO + ng * 16 * WSTRB + half * 32);
                #pragma unroll
                for (int mt = 0; mt < 2; mt++) {
                    mma16816(acc[mt][ng * 2],     Ahf[mt], Bh4);
                    mma16816(acc[mt][ng * 2 + 1], Ahf[mt], Bh4 + 2);
                    mma16816(acc[mt][ng * 2],     Ahf[mt], Bl4);
                    mma16816(acc[mt][ng * 2 + 1], Ahf[mt], Bl4 + 2);
                    mma16816(acc[mt][ng * 2],     Alf[mt], Bh4);
                    mma16816(acc[mt][ng * 2 + 1], Alf[mt], Bh4 + 2);
                }
            }
        }
        __syncthreads();
        if (c + 2 < 8) {
            #pragma unroll
            for (int t = 0; t < 4; t++) {
                int idx = tid + t * 256;
                int n = idx >> 2, seg = idx & 3;
                uint32_t d = sbase + WS_OFF + (c & 1) * WBUF + n * WSTRB + seg * 16;
                CPA16(d,       Bh + (n << 8) + (c + 2) * 32 + seg * 8);
                CPA16(d + WLO, Bl + (n << 8) + (c + 2) * 32 + seg * 8);
            }
            asm volatile("cp.async.commit_group;");
        }
    }

    // ---- epilogue ----
    // thread owns rows: wm*32 + mt*16 + h*8 + (lane>>2); cols: wn*64 + nf*8 + (lane&3)*2 (+1)
    #pragma unroll
    for (int mt = 0; mt < 2; mt++)
        #pragma unroll
        for (int nf = 0; nf < 8; nf++) {
            int col = wn * 64 + nf * 8 + (lane & 3) * 2;
            float b0 = sbias[col], b1 = sbias[col + 1];
            acc[mt][nf][0] += b0; acc[mt][nf][1] += b1;
            acc[mt][nf][2] += b0; acc[mt][nf][3] += b1;
        }

    if (PWADD) {
        #pragma unroll
        for (int mt = 0; mt < 2; mt++)
            #pragma unroll
            for (int h = 0; h < 2; h++) {
                int rloc = wm * 32 + mt * 16 + h * 8 + (lane >> 2);
                const float* base = g_PWadd + (row0 + rloc) * 256 + wn * 64 + (lane & 3) * 2;
                #pragma unroll
                for (int nf = 0; nf < 8; nf++) {
                    float2 pw = *(const float2*)(base + nf * 8);
                    acc[mt][nf][h * 2]     += pw.x;
                    acc[mt][nf][h * 2 + 1] += pw.y;
                }
            }
    }

    #pragma unroll
    for (int mt = 0; mt < 2; mt++)
        #pragma unroll
        for (int nf = 0; nf < 8; nf++)
            #pragma unroll
            for (int q = 0; q < 4; q++) {
                float v = acc[mt][nf][q];
                acc[mt][nf][q] = (ACT == 0) ? fmaxf(v, 0.f) : (v > 0.f ? v : 0.01f * v);
            }

    if (INORM) {
        #pragma unroll
        for (int mt = 0; mt < 2; mt++)
            #pragma unroll
            for (int h = 0; h < 2; h++) {
                float s1 = 0.f, s2 = 0.f;
                #pragma unroll
                for (int nf = 0; nf < 8; nf++) {
                    float a = acc[mt][nf][h * 2], b = acc[mt][nf][h * 2 + 1];
                    s1 += a + b; s2 += a * a + b * b;
                }
                s1 += __shfl_xor_sync(0xffffffffu, s1, 1);
                s2 += __shfl_xor_sync(0xffffffffu, s2, 1);
                s1 += __shfl_xor_sync(0xffffffffu, s1, 2);
                s2 += __shfl_xor_sync(0xffffffffu, s2, 2);
                if ((lane & 3) == 0) {
                    int rloc = wm * 32 + mt * 16 + h * 8 + (lane >> 2);
                    ssum[wn * 64 + rloc] = s1;
                    ssq[wn * 64 + rloc]  = s2;
                }
            }
        __syncthreads();
        if (tid < BMR) {
            float t1 = ssum[tid] + ssum[64 + tid] + ssum[128 + tid] + ssum[192 + tid];
            float t2 = ssq[tid]  + ssq[64 + tid]  + ssq[128 + tid]  + ssq[192 + tid];
            float m  = t1 * (1.f / 256.f);
            rowm[tid] = m;
            rowr[tid] = rsqrtf(t2 * (1.f / 256.f) - m * m + 1e-5f);
        }
        __syncthreads();
        #pragma unroll
        for (int mt = 0; mt < 2; mt++)
            #pragma unroll
            for (int h = 0; h < 2; h++) {
                int rloc = wm * 32 + mt * 16 + h * 8 + (lane >> 2);
                float m = rowm[rloc], rs = rowr[rloc];
                #pragma unroll
                for (int nf = 0; nf < 8; nf++) {
                    acc[mt][nf][h * 2]     = (acc[mt][nf][h * 2]     - m) * rs;
                    acc[mt][nf][h * 2 + 1] = (acc[mt][nf][h * 2 + 1] - m) * rs;
                }
            }
    }

    if (SCORE) {
        #pragma unroll
        for (int mt = 0; mt < 2; mt++)
            #pragma unroll
            for (int h = 0; h < 2; h++) {
                float p = 0.f;
                #pragma unroll
                for (int nf = 0; nf < 8; nf++) {
                    int col = wn * 64 + nf * 8 + (lane & 3) * 2;
                    p += acc[mt][nf][h * 2] * sscw[col] + acc[mt][nf][h * 2 + 1] * sscw[col + 1];
                }
                p += __shfl_xor_sync(0xffffffffu, p, 1);
                p += __shfl_xor_sync(0xffffffffu, p, 2);
                if ((lane & 3) == 0) {
                    int rloc = wm * 32 + mt * 16 + h * 8 + (lane >> 2);
                    ssum[wn * 64 + rloc] = p;
                }
            }
        __syncthreads();
        if (tid < BMR)
            g_scores[row0 + tid] = ssum[tid] + ssum[64 + tid] + ssum[128 + tid] + ssum[192 + tid]
                                 + scoreB[0];
    } else {
        #pragma unroll
        for (int mt = 0; mt < 2; mt++)
            #pragma unroll
            for (int h = 0; h < 2; h++) {
                int rloc = wm * 32 + mt * 16 + h * 8 + (lane >> 2);
                __nv_bfloat16* yh = Yh + (row0 + rloc) * 256;
                __nv_bfloat16* yl = Yl + (row0 + rloc) * 256;
                #pragma unroll
                for (int nf = 0; nf < 8; nf++) {
                    int col = wn * 64 + nf * 8 + (lane & 3) * 2;
                    float a = acc[mt][nf][h * 2], b = acc[mt][nf][h * 2 + 1];
                    __nv_bfloat16 ha = __float2bfloat16(a);
                    __nv_bfloat16 hb = __float2bfloat16(b);
                    __nv_bfloat16 la = __float2bfloat16(a - __bfloat162float(ha));
                    __nv_bfloat16 lb = __float2bfloat16(b - __bfloat162float(hb));
                    uint32_t ph = ((uint32_t)__bfloat16_as_ushort(hb) << 16) | __bfloat16_as_ushort(ha);
                    uint32_t pl = ((uint32_t)__bfloat16_as_ushort(lb) << 16) | __bfloat16_as_ushort(la);
                    *(uint32_t*)(yh + col) = ph;
                    *(uint32_t*)(yl + col) = pl;
                }
            }
    }
}

// ---------------- per-batch softmax over 4096 scores ------------------------
__global__ void softmax_kernel(float* __restrict__ probs) {
    __shared__ float sm[8];
    int b = blockIdx.x, tid = threadIdx.x;
    int wid = tid >> 5, lane = tid & 31;
    float v[16];
    float mx = -1e30f;
    #pragma unroll
    for (int i = 0; i < 16; i++) { v[i] = g_scores[b * SDIM + i * 256 + tid]; mx = fmaxf(mx, v[i]); }
    #pragma unroll
    for (int o = 16; o; o >>= 1) mx = fmaxf(mx, __shfl_xor_sync(0xffffffffu, mx, o));
    if (!lane) sm[wid] = mx;
    __syncthreads();
    mx = sm[0];
    #pragma unroll
    for (int q = 1; q < 8; q++) mx = fmaxf(mx, sm[q]);
    float s = 0.f;
    #pragma unroll
    for (int i = 0; i < 16; i++) { v[i] = expf(v[i] - mx); s += v[i]; }
    #pragma unroll
    for (int o = 16; o; o >>= 1) s += __shfl_xor_sync(0xffffffffu, s, o);
    __syncthreads();
    if (!lane) sm[wid] = s;
    __syncthreads();
    s = 0.f;
    #pragma unroll
    for (int q = 0; q < 8; q++) s += sm[q];
    float inv = 1.f / s;
    #pragma unroll
    for (int i = 0; i < 16; i++) probs[b * SDIM + i * 256 + tid] = v[i] * inv;
}

// ---------------- scatter-add weighted intensities into spectral bins --------
__global__ void scatter_kernel(const int* __restrict__ mass, const float* __restrict__ inten,
                               const float* __restrict__ probs, float* __restrict__ spect) {
    int i  = blockIdx.x * 256 + threadIdx.x;
    int bs = i >> 5;
    int b  = i >> 17;
    float w = inten[i] * probs[bs];
    atomicAdd(spect + (b << 16) + mass[i], w);
}

// ---------------- launch sequence -------------------------------------------
extern "C" void kernel_launch(void* const* d_in, const int* in_sizes, int n_in,
                              void* d_out, int out_size)
{
    const float* feat  = (const float*)d_in[0];
    const float* mask  = (const float*)d_in[1];
    const float* ohm   = (const float*)d_in[2];
    const int*   subs  = (const int*)d_in[4];
    const int*   mass  = (const int*)d_in[6];
    const float* inten = (const float*)d_in[7];
    const float* cW  = (const float*)d_in[8];
    const float* cb  = (const float*)d_in[9];
    const float* w1  = (const float*)d_in[10];
    const float* b1  = (const float*)d_in[11];
    const float* w2a = (const float*)d_in[12];
    const float* b2a = (const float*)d_in[13];
    const float* w2b = (const float*)d_in[14];
    const float* b2b = (const float*)d_in[15];
    const float* sW  = (const float*)d_in[16];
    const float* sB  = (const float*)d_in[17];

    float* out   = (float*)d_out;
    float* spect = out;                     // (B, NBINS)
    float* probs = out + BATCH * NBINS;     // (B, S)

    __nv_bfloat16 *ah0, *al0, *ah1, *al1, *ah2, *al2, *wth, *wtl;
    cudaGetSymbolAddress((void**)&ah0, g_Ah0);
    cudaGetSymbolAddress((void**)&al0, g_Al0);
    cudaGetSymbolAddress((void**)&ah1, g_Ah1);
    cudaGetSymbolAddress((void**)&al1, g_Al1);
    cudaGetSymbolAddress((void**)&ah2, g_Ah2);
    cudaGetSymbolAddress((void**)&al2, g_Al2);
    cudaGetSymbolAddress((void**)&wth, g_WTh);
    cudaGetSymbolAddress((void**)&wtl, g_WTl);

    static int attr_set = 0;
    if (!attr_set) {
        cudaFuncSetAttribute(gemm_kernel<0, true,  true,  false>, cudaFuncAttributeMaxDynamicSharedMemorySize, GEMM_DYN);
        cudaFuncSetAttribute(gemm_kernel<0, false, false, false>, cudaFuncAttributeMaxDynamicSharedMemorySize, GEMM_DYN);
        cudaFuncSetAttribute(gemm_kernel<1, false, false, false>, cudaFuncAttributeMaxDynamicSharedMemorySize, GEMM_DYN);
        cudaFuncSetAttribute(gemm_kernel<0, false, true,  true >, cudaFuncAttributeMaxDynamicSharedMemorySize, GEMM_DYN);
        cudaFuncSetAttribute(pwadd_kernel, cudaFuncAttributeMaxDynamicSharedMemorySize, 105 * 256 * 4);
        attr_set = 1;
    }

    init_pw_kernel<<<EDIM, 256>>>(cW);
    wt_kernel<<<256, 256>>>(cW + 100 * 256, 0);
    wt_kernel<<<256, 256>>>(w1,  1);
    wt_kernel<<<256, 256>>>(w2a, 2);
    wt_kernel<<<256, 256>>>(w2b, 3);
    prep_kernel<<<ROWS / TM, 256>>>(feat, mask, ohm, subs);
    pwadd_kernel<<<ROWS / 512, 256, 105 * 256 * 4>>>();

    gemm_kernel<0, true,  true,  false><<<ROWS / BMR, 256, GEMM_DYN>>>(
        ah0, al0, wth + 0 * 65536, wtl + 0 * 65536, cb,  ah1, al1, nullptr, nullptr);
    gemm_kernel<0, false, false, false><<<ROWS / BMR, 256, GEMM_DYN>>>(
        ah1, al1, wth + 1 * 65536, wtl + 1 * 65536, b1,  ah2, al2, nullptr, nullptr);
    gemm_kernel<1, false, false, false><<<ROWS / BMR, 256, GEMM_DYN>>>(
        ah2, al2, wth + 2 * 65536, wtl + 2 * 65536, b2a, ah1, al1, nullptr, nullptr);
    gemm_kernel<0, false, true,  true ><<<ROWS / BMR, 256, GEMM_DYN>>>(
        ah1, al1, wth + 3 * 65536, wtl + 3 * 65536, b2b, nullptr, nullptr, sW, sB);

    softmax_kernel<<<BATCH, 256>>>(probs);
    cudaMemsetAsync(spect, 0, (size_t)BATCH * NBINS * sizeof(float), 0);
    scatter_kernel<<<BATCH * SDIM * 32 / 256, 256>>>(mass, inten, probs, spect);
}

// round 8
// speedup vs baseline: 1.9389x; 1.2962x over previous
#include <cuda_runtime.h>
#include <cuda_bf16.h>
#include <cstdint>

#define ROWS  32768
#define BATCH 8
#define SDIM  4096
#define ADIM  48
#define GF    256
#define EDIM  5
#define NBINS 65536
#define TM    32

// gemm tiling: 64 rows x 256 cols, K chunked by 32, X+W double buffered
#define BMR    64
#define CK     32
#define STRB   80                     // smem row stride bytes (40 bf16, conflict-free)
#define XL_O   5120                   // 64*80
#define WH_O   10240
#define WL_O   30720
#define SLOT   51200
#define GEMM_DYN (2 * SLOT)           // 102400 -> 2 CTAs/SM

typedef unsigned long long ull;

// ---------------- scratch (static device globals; no allocation) -------------
__device__ __nv_bfloat16 g_Ah0[ROWS * 256], g_Al0[ROWS * 256];
__device__ __nv_bfloat16 g_Ah1[ROWS * 256], g_Al1[ROWS * 256];
__device__ __nv_bfloat16 g_Ah2[ROWS * 256], g_Al2[ROWS * 256];
__device__ __nv_bfloat16 g_WTh[4][256 * 256], g_WTl[4][256 * 256];
__device__ float g_PWadd[ROWS * 256];
__device__ float g_scores[ROWS];
__device__ float g_PW[EDIM * 21 * 256];

// ---------------- helpers ----------------------------------------------------
__device__ __forceinline__ uint32_t smem_u32(const void* p) {
    uint32_t a;
    asm("{ .reg .u64 t; cvta.to.shared.u64 t, %1; cvt.u32.u64 %0, t; }" : "=r"(a) : "l"(p));
    return a;
}
__device__ __forceinline__ void ldsm4(uint32_t* r, uint32_t a) {
    asm volatile("ldmatrix.sync.aligned.m8n8.x4.shared.b16 {%0,%1,%2,%3}, [%4];"
                 : "=r"(r[0]), "=r"(r[1]), "=r"(r[2]), "=r"(r[3]) : "r"(a));
}
__device__ __forceinline__ void mma16816(float* d, const uint32_t* a, const uint32_t* b) {
    asm volatile("mma.sync.aligned.m16n8k16.row.col.f32.bf16.bf16.f32 "
                 "{%0,%1,%2,%3}, {%4,%5,%6,%7}, {%8,%9}, {%0,%1,%2,%3};"
                 : "+f"(d[0]), "+f"(d[1]), "+f"(d[2]), "+f"(d[3])
                 : "r"(a[0]), "r"(a[1]), "r"(a[2]), "r"(a[3]), "r"(b[0]), "r"(b[1]));
}
#define CPA16(dst, src) \
    asm volatile("cp.async.ca.shared.global [%0], [%1], 16;" :: "r"(dst), "l"(src))

// ---------------- prefix-sum of the one-hot block of combine_W ---------------
__global__ void init_pw_kernel(const float* __restrict__ cW) {
    int e = blockIdx.x, j = threadIdx.x;
    float run = 0.f;
    g_PW[(e * 21 + 0) * 256 + j] = 0.f;
    for (int l = 0; l < 20; l++) {
        run += cW[(e * 20 + l) * 256 + j];
        g_PW[(e * 21 + l + 1) * 256 + j] = run;
    }
}

// ---------------- all 4 W^T + bf16 hi/lo splits, coalesced transpose ---------
__global__ __launch_bounds__(256) void wt_all_kernel(
    const float* __restrict__ cW, const float* __restrict__ w1,
    const float* __restrict__ w2a, const float* __restrict__ w2b)
{
    __shared__ float tile[32][33];
    int layer = blockIdx.x >> 6;
    int t     = blockIdx.x & 63;
    int kt    = (t >> 3) << 5;
    int nt    = (t & 7) << 5;
    const float* W = layer == 0 ? cW + 100 * 256 : layer == 1 ? w1 : layer == 2 ? w2a : w2b;
    int lx = threadIdx.x & 31, ly = threadIdx.x >> 5;
    #pragma unroll
    for (int i = 0; i < 4; i++)
        tile[ly + i * 8][lx] = W[(kt + ly + i * 8) * 256 + nt + lx];
    __syncthreads();
    #pragma unroll
    for (int i = 0; i < 4; i++) {
        int n = nt + ly + i * 8;
        float w = tile[lx][ly + i * 8];
        __nv_bfloat16 h = __float2bfloat16(w);
        g_WTh[layer][n * 256 + kt + lx] = h;
        g_WTl[layer][n * 256 + kt + lx] = __float2bfloat16(w - __bfloat162float(h));
    }
}

// ---------------- prep: subset mean + inorm + counts + thermometer add -------
__global__ __launch_bounds__(256) void prep_kernel(
    const float* __restrict__ feat, const float* __restrict__ mask,
    const float* __restrict__ ohmat, const int* __restrict__ subs)
{
    __shared__ float ys[TM * 256];
    __shared__ float subm[TM * ADIM];
    __shared__ float sraw[TM * ADIM];
    __shared__ float smask[ADIM];
    __shared__ float sohs[ADIM * EDIM];
    __shared__ float sinv[TM];
    __shared__ float rowm[TM], rowr[TM];
    __shared__ int   scnt[TM * EDIM];

    int tid  = threadIdx.x;
    int row0 = blockIdx.x * TM;
    int b    = row0 >> 12;

    if (tid < ADIM) smask[tid] = mask[b * ADIM + tid];
    for (int idx = tid; idx < ADIM * EDIM; idx += 256)
        sohs[idx] = ohmat[b * ADIM * EDIM + idx];
    __syncthreads();

    for (int idx = tid; idx < TM * ADIM; idx += 256) {
        int r = idx / ADIM, a = idx - r * ADIM;
        float v = (float)subs[(row0 + r) * ADIM + a];
        sraw[idx] = v;
        subm[idx] = v * smask[a];
    }
    __syncthreads();

    if (tid < TM * EDIM) {
        int r = tid / EDIM, e = tid - r * EDIM;
        float c = 0.f;
        for (int a = 0; a < ADIM; a++) c += sohs[a * EDIM + e] * sraw[r * ADIM + a];
        int ci = (int)(c + 0.5f);
        scnt[tid] = ci > 20 ? 20 : ci;
    }
    if (tid < TM) {
        float sz = 0.f;
        for (int a = 0; a < ADIM; a++) sz += subm[tid * ADIM + a];
        sinv[tid] = 1.f / (sz + 1e-4f);
    }
    __syncthreads();

    // thermometer additive term for this block's 32 rows (coalesced PW gathers)
    #pragma unroll 4
    for (int r = 0; r < TM; r++) {
        float s = 0.f;
        #pragma unroll
        for (int e = 0; e < EDIM; e++)
            s += g_PW[(e * 21 + scnt[r * EDIM + e]) * 256 + tid];
        g_PWadd[(row0 + r) * 256 + tid] = s;
    }

    float acc[TM];
    #pragma unroll
    for (int r = 0; r < TM; r++) acc[r] = 0.f;
    const float* fb = feat + b * ADIM * GF + tid;
    for (int a = 0; a < ADIM; a++) {
        float f = fb[a * GF] * smask[a];
        #pragma unroll
        for (int r = 0; r < TM; r++) acc[r] += f * subm[r * ADIM + a];
    }
    #pragma unroll
    for (int r = 0; r < TM; r++) { acc[r] *= sinv[r]; ys[r * 256 + tid] = acc[r]; }
    __syncthreads();

    int wid = tid >> 5, lane = tid & 31;
    for (int i = 0; i < 4; i++) {
        int r = wid * 4 + i;
        float s1 = 0.f, s2 = 0.f;
        #pragma unroll
        for (int q = 0; q < 8; q++) { float x = ys[r * 256 + lane + q * 32]; s1 += x; s2 += x * x; }
        #pragma unroll
        for (int o = 16; o; o >>= 1) {
            s1 += __shfl_xor_sync(0xffffffffu, s1, o);
            s2 += __shfl_xor_sync(0xffffffffu, s2, o);
        }
        if (!lane) {
            float m = s1 * (1.f / 256.f);
            rowm[r] = m;
            rowr[r] = rsqrtf(s2 * (1.f / 256.f) - m * m + 1e-5f);
        }
    }
    __syncthreads();
    #pragma unroll
    for (int r = 0; r < TM; r++) {
        float xv = (acc[r] - rowm[r]) * rowr[r];
        __nv_bfloat16 h = __float2bfloat16(xv);
        int o = (row0 + r) * 256 + tid;
        g_Ah0[o] = h;
        g_Al0[o] = __float2bfloat16(xv - __bfloat162float(h));
    }
}

// ---------------- HMMA bf16x3 GEMM: X+W double-buffered 32-k chunks ----------
template <int ACT, bool PWADD, bool INORM, bool SCORE>
__global__ __launch_bounds__(256, 2) void gemm_kernel(
    const __nv_bfloat16* __restrict__ Ah, const __nv_bfloat16* __restrict__ Al,
    const __nv_bfloat16* __restrict__ Bh, const __nv_bfloat16* __restrict__ Bl,
    const float* __restrict__ bias,
    __nv_bfloat16* __restrict__ Yh, __nv_bfloat16* __restrict__ Yl,
    const float* __restrict__ scoreW, const float* __restrict__ scoreB)
{
    extern __shared__ unsigned char dsm[];
    __shared__ float sbias[256];
    __shared__ float sscw[256];
    __shared__ float ssum[256], ssq[256];
    __shared__ float rowm[BMR], rowr[BMR];

    int tid  = threadIdx.x;
    int wid  = tid >> 5, lane = tid & 31;
    int wm   = wid & 1;                 // 2 row-groups of 32
    int wn   = wid >> 1;                // 4 col-groups of 64
    int row0 = blockIdx.x * BMR;
    uint32_t sbase = smem_u32(dsm);

    sbias[tid] = bias[tid];
    if (SCORE) sscw[tid] = scoreW[tid];

    // per-thread staging indices
    int xr = tid >> 2, xseg = tid & 3;            // X: 64 rows x 4 segs

    // stage chunk c into slot s
    #define STAGE(c, s) do {                                                        \
        uint32_t bb = sbase + (s) * SLOT;                                           \
        CPA16(bb + xr * STRB + xseg * 16,        Ah + ((row0 + xr) << 8) + (c) * CK + xseg * 8); \
        CPA16(bb + XL_O + xr * STRB + xseg * 16, Al + ((row0 + xr) << 8) + (c) * CK + xseg * 8); \
        _Pragma("unroll")                                                           \
        for (int t = 0; t < 4; t++) {                                               \
            int idx = tid + t * 256;                                                \
            int n = idx >> 2, sg = idx & 3;                                         \
            CPA16(bb + WH_O + n * STRB + sg * 16, Bh + (n << 8) + (c) * CK + sg * 8); \
            CPA16(bb + WL_O + n * STRB + sg * 16, Bl + (n << 8) + (c) * CK + sg * 8); \
        }                                                                           \
        asm volatile("cp.async.commit_group;");                                     \
    } while (0)

    STAGE(0, 0);
    STAGE(1, 1);

    // lane-level ldmatrix offsets within a slot
    uint32_t xoff = (wm * 32 + (lane & 15)) * STRB + (lane >> 4) * 16;
    uint32_t woff = WH_O + (wn * 64 + (lane & 7) + ((lane >> 4) & 1) * 8) * STRB
                  + ((lane >> 3) & 1) * 16;

    float acc[2][8][4];
    #pragma unroll
    for (int mt = 0; mt < 2; mt++)
        #pragma unroll
        for (int nf = 0; nf < 8; nf++)
            #pragma unroll
            for (int q = 0; q < 4; q++) acc[mt][nf][q] = 0.f;

    for (int c = 0; c < 8; c++) {
        if (c < 7) asm volatile("cp.async.wait_group 1;" ::: "memory");
        else       asm volatile("cp.async.wait_group 0;" ::: "memory");
        __syncthreads();
        uint32_t slot = sbase + (c & 1) * SLOT;
        uint32_t xaH = slot + xoff, xaL = xaH + XL_O;
        uint32_t waH = slot + woff, waL = waH + 20480;

        #pragma unroll
        for (int half = 0; half < 2; half++) {
            uint32_t Ahf[2][4], Alf[2][4];
            ldsm4(Ahf[0], xaH + half * 32);
            ldsm4(Ahf[1], xaH + 16 * STRB + half * 32);
            ldsm4(Alf[0], xaL + half * 32);
            ldsm4(Alf[1], xaL + 16 * STRB + half * 32);
            #pragma unroll
            for (int ng = 0; ng < 4; ng++) {
                uint32_t Bh4[4], Bl4[4];
                ldsm4(Bh4, waH + ng * 16 * STRB + half * 32);
                ldsm4(Bl4, waL + ng * 16 * STRB + half * 32);
                #pragma unroll
                for (int mt = 0; mt < 2; mt++) {
                    mma16816(acc[mt][ng * 2],     Ahf[mt], Bh4);
                    mma16816(acc[mt][ng * 2 + 1], Ahf[mt], Bh4 + 2);
                    mma16816(acc[mt][ng * 2],     Ahf[mt], Bl4);
                    mma16816(acc[mt][ng * 2 + 1], Ahf[mt], Bl4 + 2);
                    mma16816(acc[mt][ng * 2],     Alf[mt], Bh4);
                    mma16816(acc[mt][ng * 2 + 1], Alf[mt], Bh4 + 2);
                }
            }
        }
        __syncthreads();
        if (c + 2 < 8) STAGE(c + 2, c & 1);
    }
    #undef STAGE

    // ---- epilogue (verified mapping from R7) ----
    #pragma unroll
    for (int mt = 0; mt < 2; mt++)
        #pragma unroll
        for (int nf = 0; nf < 8; nf++) {
            int col = wn * 64 + nf * 8 + (lane & 3) * 2;
            float b0 = sbias[col], b1 = sbias[col + 1];
            acc[mt][nf][0] += b0; acc[mt][nf][1] += b1;
            acc[mt][nf][2] += b0; acc[mt][nf][3] += b1;
        }

    if (PWADD) {
        #pragma unroll
        for (int mt = 0; mt < 2; mt++)
            #pragma unroll
            for (int h = 0; h < 2; h++) {
                int rloc = wm * 32 + mt * 16 + h * 8 + (lane >> 2);
                const float* base = g_PWadd + (row0 + rloc) * 256 + wn * 64 + (lane & 3) * 2;
                #pragma unroll
                for (int nf = 0; nf < 8; nf++) {
                    float2 pw = *(const float2*)(base + nf * 8);
                    acc[mt][nf][h * 2]     += pw.x;
                    acc[mt][nf][h * 2 + 1] += pw.y;
                }
            }
    }

    #pragma unroll
    for (int mt = 0; mt < 2; mt++)
        #pragma unroll
        for (int nf = 0; nf < 8; nf++)
            #pragma unroll
            for (int q = 0; q < 4; q++) {
                float v = acc[mt][nf][q];
                acc[mt][nf][q] = (ACT == 0) ? fmaxf(v, 0.f) : (v > 0.f ? v : 0.01f * v);
            }

    if (INORM) {
        #pragma unroll
        for (int mt = 0; mt < 2; mt++)
            #pragma unroll
            for (int h = 0; h < 2; h++) {
                float s1 = 0.f, s2 = 0.f;
                #pragma unroll
                for (int nf = 0; nf < 8; nf++) {
                    float a = acc[mt][nf][h * 2], b = acc[mt][nf][h * 2 + 1];
                    s1 += a + b; s2 += a * a + b * b;
                }
                s1 += __shfl_xor_sync(0xffffffffu, s1, 1);
                s2 += __shfl_xor_sync(0xffffffffu, s2, 1);
                s1 += __shfl_xor_sync(0xffffffffu, s1, 2);
                s2 += __shfl_xor_sync(0xffffffffu, s2, 2);
                if ((lane & 3) == 0) {
                    int rloc = wm * 32 + mt * 16 + h * 8 + (lane >> 2);
                    ssum[wn * 64 + rloc] = s1;
                    ssq[wn * 64 + rloc]  = s2;
                }
            }
        __syncthreads();
        if (tid < BMR) {
            float t1 = ssum[tid] + ssum[64 + tid] + ssum[128 + tid] + ssum[192 + tid];
            float t2 = ssq[tid]  + ssq[64 + tid]  + ssq[128 + tid]  + ssq[192 + tid];
            float m  = t1 * (1.f / 256.f);
            rowm[tid] = m;
            rowr[tid] = rsqrtf(t2 * (1.f / 256.f) - m * m + 1e-5f);
        }
        __syncthreads();
        #pragma unroll
        for (int mt = 0; mt < 2; mt++)
            #pragma unroll
            for (int h = 0; h < 2; h++) {
                int rloc = wm * 32 + mt * 16 + h * 8 + (lane >> 2);
                float m = rowm[rloc], rs = rowr[rloc];
                #pragma unroll
                for (int nf = 0; nf < 8; nf++) {
                    acc[mt][nf][h * 2]     = (acc[mt][nf][h * 2]     - m) * rs;
                    acc[mt][nf][h * 2 + 1] = (acc[mt][nf][h * 2 + 1] - m) * rs;
                }
            }
    }

    if (SCORE) {
        #pragma unroll
        for (int mt = 0; mt < 2; mt++)
            #pragma unroll
            for (int h = 0; h < 2; h++) {
                float p = 0.f;
                #pragma unroll
                for (int nf = 0; nf < 8; nf++) {
                    int col = wn * 64 + nf * 8 + (lane & 3) * 2;
                    p += acc[mt][nf][h * 2] * sscw[col] + acc[mt][nf][h * 2 + 1] * sscw[col + 1];
                }
                p += __shfl_xor_sync(0xffffffffu, p, 1);
                p += __shfl_xor_sync(0xffffffffu, p, 2);
                if ((lane & 3) == 0) {
                    int rloc = wm * 32 + mt * 16 + h * 8 + (lane >> 2);
                    ssum[wn * 64 + rloc] = p;
                }
            }
        __syncthreads();
        if (tid < BMR)
            g_scores[row0 + tid] = ssum[tid] + ssum[64 + tid] + ssum[128 + tid] + ssum[192 + tid]
                                 + scoreB[0];
    } else {
        #pragma unroll
        for (int mt = 0; mt < 2; mt++)
            #pragma unroll
            for (int h = 0; h < 2; h++) {
                int rloc = wm * 32 + mt * 16 + h * 8 + (lane >> 2);
                __nv_bfloat16* yh = Yh + (row0 + rloc) * 256;
                __nv_bfloat16* yl = Yl + (row0 + rloc) * 256;
                #pragma unroll
                for (int nf = 0; nf < 8; nf++) {
                    int col = wn * 64 + nf * 8 + (lane & 3) * 2;
                    float a = acc[mt][nf][h * 2], b = acc[mt][nf][h * 2 + 1];
                    __nv_bfloat16 ha = __float2bfloat16(a);
                    __nv_bfloat16 hb = __float2bfloat16(b);
                    __nv_bfloat16 la = __float2bfloat16(a - __bfloat162float(ha));
                    __nv_bfloat16 lb = __float2bfloat16(b - __bfloat162float(hb));
                    uint32_t ph = ((uint32_t)__bfloat16_as_ushort(hb) << 16) | __bfloat16_as_ushort(ha);
                    uint32_t pl = ((uint32_t)__bfloat16_as_ushort(lb) << 16) | __bfloat16_as_ushort(la);
                    *(uint32_t*)(yh + col) = ph;
                    *(uint32_t*)(yl + col) = pl;
                }
            }
    }
}

// ---------------- per-batch softmax over 4096 scores ------------------------
__global__ void softmax_kernel(float* __restrict__ probs) {
    __shared__ float sm[8];
    int b = blockIdx.x, tid = threadIdx.x;
    int wid = tid >> 5, lane = tid & 31;
    float v[16];
    float mx = -1e30f;
    #pragma unroll
    for (int i = 0; i < 16; i++) { v[i] = g_scores[b * SDIM + i * 256 + tid]; mx = fmaxf(mx, v[i]); }
    #pragma unroll
    for (int o = 16; o; o >>= 1) mx = fmaxf(mx, __shfl_xor_sync(0xffffffffu, mx, o));
    if (!lane) sm[wid] = mx;
    __syncthreads();
    mx = sm[0];
    #pragma unroll
    for (int q = 1; q < 8; q++) mx = fmaxf(mx, sm[q]);
    float s = 0.f;
    #pragma unroll
    for (int i = 0; i < 16; i++) { v[i] = expf(v[i] - mx); s += v[i]; }
    #pragma unroll
    for (int o = 16; o; o >>= 1) s += __shfl_xor_sync(0xffffffffu, s, o);
    __syncthreads();
    if (!lane) sm[wid] = s;
    __syncthreads();
    s = 0.f;
    #pragma unroll
    for (int q = 0; q < 8; q++) s += sm[q];
    float inv = 1.f / s;
    #pragma unroll
    for (int i = 0; i < 16; i++) probs[b * SDIM + i * 256 + tid] = v[i] * inv;
}

// ---------------- scatter-add weighted intensities into spectral bins --------
__global__ void scatter_kernel(const int* __restrict__ mass, const float* __restrict__ inten,
                               const float* __restrict__ probs, float* __restrict__ spect) {
    int i  = blockIdx.x * 256 + threadIdx.x;
    int bs = i >> 5;
    int b  = i >> 17;
    float w = inten[i] * probs[bs];
    atomicAdd(spect + (b << 16) + mass[i], w);
}

// ---------------- launch sequence -------------------------------------------
extern "C" void kernel_launch(void* const* d_in, const int* in_sizes, int n_in,
                              void* d_out, int out_size)
{
    const float* feat  = (const float*)d_in[0];
    const float* mask  = (const float*)d_in[1];
    const float* ohm   = (const float*)d_in[2];
    const int*   subs  = (const int*)d_in[4];
    const int*   mass  = (const int*)d_in[6];
    const float* inten = (const float*)d_in[7];
    const float* cW  = (const float*)d_in[8];
    const float* cb  = (const float*)d_in[9];
    const float* w1  = (const float*)d_in[10];
    const float* b1  = (const float*)d_in[11];
    const float* w2a = (const float*)d_in[12];
    const float* b2a = (const float*)d_in[13];
    const float* w2b = (const float*)d_in[14];
    const float* b2b = (const float*)d_in[15];
    const float* sW  = (const float*)d_in[16];
    const float* sB  = (const float*)d_in[17];

    float* out   = (float*)d_out;
    float* spect = out;                     // (B, NBINS)
    float* probs = out + BATCH * NBINS;     // (B, S)

    __nv_bfloat16 *ah0, *al0, *ah1, *al1, *ah2, *al2, *wth, *wtl;
    cudaGetSymbolAddress((void**)&ah0, g_Ah0);
    cudaGetSymbolAddress((void**)&al0, g_Al0);
    cudaGetSymbolAddress((void**)&ah1, g_Ah1);
    cudaGetSymbolAddress((void**)&al1, g_Al1);
    cudaGetSymbolAddress((void**)&ah2, g_Ah2);
    cudaGetSymbolAddress((void**)&al2, g_Al2);
    cudaGetSymbolAddress((void**)&wth, g_WTh);
    cudaGetSymbolAddress((void**)&wtl, g_WTl);

    static int attr_set = 0;
    if (!attr_set) {
        cudaFuncSetAttribute(gemm_kernel<0, true,  true,  false>, cudaFuncAttributeMaxDynamicSharedMemorySize, GEMM_DYN);
        cudaFuncSetAttribute(gemm_kernel<0, false, false, false>, cudaFuncAttributeMaxDynamicSharedMemorySize, GEMM_DYN);
        cudaFuncSetAttribute(gemm_kernel<1, false, false, false>, cudaFuncAttributeMaxDynamicSharedMemorySize, GEMM_DYN);
        cudaFuncSetAttribute(gemm_kernel<0, false, true,  true >, cudaFuncAttributeMaxDynamicSharedMemorySize, GEMM_DYN);
        attr_set = 1;
    }

    // launch order tuned so the fixed ncu capture window (4th launch) hits gemm layer 0
    init_pw_kernel<<<EDIM, 256>>>(cW);                                   // 1
    wt_all_kernel<<<256, 256>>>(cW, w1, w2a, w2b);                       // 2
    prep_kernel<<<ROWS / TM, 256>>>(feat, mask, ohm, subs);              // 3

    gemm_kernel<0, true,  true,  false><<<ROWS / BMR, 256, GEMM_DYN>>>( // 4 (captured)
        ah0, al0, wth + 0 * 65536, wtl + 0 * 65536, cb,  ah1, al1, nullptr, nullptr);
    gemm_kernel<0, false, false, false><<<ROWS / BMR, 256, GEMM_DYN>>>(
        ah1, al1, wth + 1 * 65536, wtl + 1 * 65536, b1,  ah2, al2, nullptr, nullptr);
    gemm_kernel<1, false, false, false><<<ROWS / BMR, 256, GEMM_DYN>>>(
        ah2, al2, wth + 2 * 65536, wtl + 2 * 65536, b2a, ah1, al1, nullptr, nullptr);
    gemm_kernel<0, false, true,  true ><<<ROWS / BMR, 256, GEMM_DYN>>>(
        ah1, al1, wth + 3 * 65536, wtl + 3 * 65536, b2b, nullptr, nullptr, sW, sB);

    softmax_kernel<<<BATCH, 256>>>(probs);
    cudaMemsetAsync(spect, 0, (size_t)BATCH * NBINS * sizeof(float), 0);
    scatter_kernel<<<BATCH * SDIM * 32 / 256, 256>>>(mass, inten, probs, spect);
}